// round 7
// baseline (speedup 1.0000x reference)
#include <cuda_runtime.h>
#include <cuda_bf16.h>
#include <cstdint>
#include <math.h>

#define ENC 2048
#define DEC 512
#define ATTD 512
#define BATCH 256
#define LSEQ 196
#define MROWS (BATCH * LSEQ)      // 50176
#define TILE_M 128
#define NCTA (MROWS / TILE_M)     // 392
#define KBLK 32
#define NKB (ENC / KBLK)          // 64
#define NB_CHUNKS 4               // 512 / 128
#define NSTG 3
#define XSTG 16384                // x: 128 rows x 32k x 2B x 2(hi/lo)
#define WSTG 16384                // W: 128 rows x 32k x 2B x 2(hi/lo)
#define WBASE (NSTG * XSTG)       // 49152
#define DYN_BYTES (WBASE + NSTG * WSTG + 128)  // 98432

// ---------------- scratch globals ----------------
__device__ float g_att2[BATCH * ATTD];
__device__ float g_gate[BATCH];
__device__ float g_att[MROWS];
// W transposed + bf16-split: [hl][n=512][k=2048] bf16
__device__ __align__(16) unsigned char g_Wt[2u * 512u * 2048u * 2u];

// ---------------- helpers ----------------
__device__ __forceinline__ uint32_t smem_u32(const void* p) {
    uint32_t a;
    asm("{ .reg .u64 t; cvta.to.shared.u64 t, %1; cvt.u32.u64 %0, t; }" : "=r"(a) : "l"(p));
    return a;
}
__device__ __forceinline__ uint32_t pack2(float a, float b) {
    __nv_bfloat162 t = __floats2bfloat162_rn(a, b);
    return *reinterpret_cast<uint32_t*>(&t);
}
#define LDSM_X4(r, addr) \
    asm volatile("ldmatrix.sync.aligned.m8n8.x4.shared.b16 {%0,%1,%2,%3}, [%4];" \
        : "=r"((r)[0]), "=r"((r)[1]), "=r"((r)[2]), "=r"((r)[3]) : "r"(addr))
#define MMA_BF16(c, a, b) \
    asm volatile("mma.sync.aligned.m16n8k16.row.col.f32.bf16.bf16.f32 " \
        "{%0,%1,%2,%3}, {%4,%5,%6,%7}, {%8,%9}, {%0,%1,%2,%3};" \
        : "+f"((c)[0]), "+f"((c)[1]), "+f"((c)[2]), "+f"((c)[3]) \
        : "r"((a)[0]), "r"((a)[1]), "r"((a)[2]), "r"((a)[3]), "r"((b)[0]), "r"((b)[1]))
#define CP_ASYNC16(dst, src) \
    asm volatile("cp.async.ca.shared.global [%0], [%1], 16;" :: "r"(dst), "l"(src) : "memory")
#define CP_COMMIT() asm volatile("cp.async.commit_group;" ::: "memory")
#define CP_WAIT1()  asm volatile("cp.async.wait_group 1;" ::: "memory")
#define CP_WAIT0()  asm volatile("cp.async.wait_group 0;" ::: "memory")

// ---------------------------------------------------------------------------
// prep_w: W_enc [2048 k][512 n] fp32 -> g_Wt bf16 [hl][n][k]
// ---------------------------------------------------------------------------
__global__ __launch_bounds__(256) void prep_w(const float* __restrict__ W_enc) {
    __shared__ float tile[64][65];
    const int k0 = blockIdx.x * 64, n0 = blockIdx.y * 64;
    const int tid = threadIdx.x;
    for (int i = tid; i < 64 * 64; i += 256) {
        int kk = i >> 6, nn = i & 63;
        tile[kk][nn] = W_enc[(size_t)(k0 + kk) * ATTD + n0 + nn];
    }
    __syncthreads();
    for (int i = tid; i < 1024; i += 256) {
        int hl = i >> 9, rem = i & 511;
        int nn = rem >> 3, ch = rem & 7;
        uint32_t w[4];
#pragma unroll
        for (int j = 0; j < 4; j++) {
            float v0 = tile[ch * 8 + 2 * j][nn], v1 = tile[ch * 8 + 2 * j + 1][nn];
            float h0 = __bfloat162float(__float2bfloat16_rn(v0));
            float h1 = __bfloat162float(__float2bfloat16_rn(v1));
            w[j] = hl ? pack2(v0 - h0, v1 - h1) : pack2(h0, h1);
        }
        *reinterpret_cast<uint4*>(g_Wt + (size_t)hl * 2097152 +
                                  (size_t)(n0 + nn) * 4096 + (size_t)(k0 + ch * 8) * 2) =
            make_uint4(w[0], w[1], w[2], w[3]);
    }
}

// ---------------------------------------------------------------------------
// att2 + gate
// ---------------------------------------------------------------------------
__global__ __launch_bounds__(256) void att2_kernel(
    const float* __restrict__ h, const float* __restrict__ W_dec,
    const float* __restrict__ b_dec, const float* __restrict__ b_enc,
    const float* __restrict__ W_beta, const float* __restrict__ b_beta) {
    int b = blockIdx.x, t = threadIdx.x;
    __shared__ float hs[DEC];
    __shared__ float red[256];
    hs[t] = h[b * DEC + t];
    hs[t + 256] = h[b * DEC + t + 256];
    __syncthreads();
    float acc0 = 0.f, acc1 = 0.f;
#pragma unroll 8
    for (int k = 0; k < DEC; k++) {
        float hv = hs[k];
        acc0 += hv * W_dec[k * ATTD + t];
        acc1 += hv * W_dec[k * ATTD + t + 256];
    }
    g_att2[b * ATTD + t] = acc0 + b_dec[t] + b_enc[t];
    g_att2[b * ATTD + t + 256] = acc1 + b_dec[t + 256] + b_enc[t + 256];
    float p = hs[t] * W_beta[t] + hs[t + 256] * W_beta[t + 256];
    red[t] = p;
    __syncthreads();
    for (int s = 128; s > 0; s >>= 1) {
        if (t < s) red[t] += red[t + s];
        __syncthreads();
    }
    if (t == 0) g_gate[b] = 1.f / (1.f + expf(-(red[0] + b_beta[0])));
}

// ---------------------------------------------------------------------------
// Main GEMM: 3-pass bf16 mma.sync, 3-stage pipeline, 2 CTAs/SM.
// 8 warps = 2(m) x 4(n); warp tile m64 x n32. 4 n-chunks of 128.
// x converted fp32->bf16 hi/lo in-loop (proven free under HMMA).
// ---------------------------------------------------------------------------
__global__ __launch_bounds__(256, 2) void att_gemm_mma(
    const float* __restrict__ x, const float* __restrict__ W_full) {
    extern __shared__ unsigned char dynraw[];
    __shared__ float wf_s[ATTD];
    __shared__ float att_acc[TILE_M];

    const int tid = threadIdx.x;
    const int lane = tid & 31;
    const int wid = tid >> 5;
    const int wm = wid >> 2;   // 0..1
    const int wn = wid & 3;    // 0..3
    const int row0 = blockIdx.x * TILE_M;

    uint32_t rawb = smem_u32(dynraw);
    uint32_t dynb = (rawb + 127u) & ~127u;
    unsigned char* dyn = dynraw + (dynb - rawb);

    for (int i = tid; i < ATTD; i += 256) wf_s[i] = W_full[i];
    if (tid < TILE_M) att_acc[tid] = 0.f;
    __syncthreads();

    // ---- x loader: thread -> (row xm, k-half xh2 of 16 fp32 elems) ----
    const int xm = tid >> 1, xh2 = tid & 1;
    const int xsw = (xm >> 1) & 3;
    const float4* xg = reinterpret_cast<const float4*>(x) +
                       ((size_t)(row0 + xm) * ENC) / 4 + xh2 * 4;

    // ldmatrix lane geometry (2m x 4n; warp tile m64 x n32)
    const int a_r = wm * 64 + (lane & 7) + (lane & 8);
    const int a_hi = lane >> 4;
    const int b_r = wn * 32 + (lane & 7) + ((lane >> 1) & 8);
    const int b_hi = (lane >> 3) & 1;

    for (int nb = 0; nb < NB_CHUNKS; nb++) {
        float acc[4][4][4];
#pragma unroll
        for (int mt = 0; mt < 4; mt++)
#pragma unroll
            for (int nt = 0; nt < 4; nt++)
#pragma unroll
                for (int q = 0; q < 4; q++) acc[mt][nt][q] = 0.f;

        // ---- prologue ----
        {   // x stage 0: LDG + cvt + STS
            float4 x0[4];
#pragma unroll
            for (int j = 0; j < 4; j++) x0[j] = xg[j];
            const float* e = reinterpret_cast<const float*>(x0);
            uint32_t hw[8], lw[8];
#pragma unroll
            for (int q = 0; q < 8; q++) {
                float v0 = e[2 * q], v1 = e[2 * q + 1];
                float h0 = __bfloat162float(__float2bfloat16_rn(v0));
                float h1 = __bfloat162float(__float2bfloat16_rn(v1));
                hw[q] = pack2(h0, h1);
                lw[q] = pack2(v0 - h0, v1 - h1);
            }
#pragma unroll
            for (int j = 0; j < 2; j++) {
                int swo = xm * 64 + (((xh2 * 2 + j) ^ xsw) << 4);
                *reinterpret_cast<uint4*>(dyn + swo) =
                    make_uint4(hw[4 * j], hw[4 * j + 1], hw[4 * j + 2], hw[4 * j + 3]);
                *reinterpret_cast<uint4*>(dyn + 8192 + swo) =
                    make_uint4(lw[4 * j], lw[4 * j + 1], lw[4 * j + 2], lw[4 * j + 3]);
            }
        }
        // W stages 0, 1 via cp.async (one commit group each)
#pragma unroll
        for (int p = 0; p < 2; p++) {
#pragma unroll
            for (int hl = 0; hl < 2; hl++)
#pragma unroll
                for (int j = 0; j < 2; j++) {
                    int i = tid + 256 * j;
                    int row = i >> 2, c = i & 3;
                    uint32_t dst = dynb + WBASE + p * WSTG + hl * 8192 +
                                   row * 64 + ((c ^ ((row >> 1) & 3)) << 4);
                    const unsigned char* src = g_Wt + (size_t)hl * 2097152 +
                        (size_t)(nb * 128 + row) * 4096 + (size_t)(p * KBLK + c * 8) * 2;
                    CP_ASYNC16(dst, src);
                }
            CP_COMMIT();
        }

        for (int kblk = 0; kblk < NKB; kblk++) {
            const int st = kblk % NSTG;
            const bool more = (kblk + 1 < NKB);
            float4 xr[4];
            if (more) {
                const float4* p = xg + (kblk + 1) * (KBLK / 4);
#pragma unroll
                for (int j = 0; j < 4; j++) xr[j] = p[j];
            }
            CP_WAIT1();
            __syncthreads();   // W(kblk) + x(kblk) visible

            // cp.async W(kblk+2) into stage (kblk+2)%3 (or empty group)
            if (kblk + 2 < NKB) {
                const int ws = (kblk + 2) % NSTG;
#pragma unroll
                for (int hl = 0; hl < 2; hl++)
#pragma unroll
                    for (int j = 0; j < 2; j++) {
                        int i = tid + 256 * j;
                        int row = i >> 2, c = i & 3;
                        uint32_t dst = dynb + WBASE + ws * WSTG + hl * 8192 +
                                       row * 64 + ((c ^ ((row >> 1) & 3)) << 4);
                        const unsigned char* src = g_Wt + (size_t)hl * 2097152 +
                            (size_t)(nb * 128 + row) * 4096 +
                            (size_t)((kblk + 2) * KBLK + c * 8) * 2;
                        CP_ASYNC16(dst, src);
                    }
            }
            CP_COMMIT();

            // ---- MMA on stage st ----
            {
                const uint32_t xsb = dynb + st * XSTG;
                const uint32_t wsb = dynb + WBASE + st * WSTG;
#pragma unroll
                for (int ks = 0; ks < 2; ks++) {
                    uint32_t ah[4][4], al[4][4];
#pragma unroll
                    for (int mt = 0; mt < 4; mt++) {
                        int row = a_r + mt * 16;
                        uint32_t ad = xsb + row * 64 +
                                      (((ks * 2 + a_hi) ^ ((row >> 1) & 3)) << 4);
                        LDSM_X4(ah[mt], ad);
                        LDSM_X4(al[mt], ad + 8192);
                    }
#pragma unroll
                    for (int ntp = 0; ntp < 2; ntp++) {
                        int row = b_r + ntp * 16;
                        uint32_t bd = wsb + row * 64 +
                                      (((ks * 2 + b_hi) ^ ((row >> 1) & 3)) << 4);
                        uint32_t bh[4], bl[4];
                        LDSM_X4(bh, bd);
                        LDSM_X4(bl, bd + 8192);
#pragma unroll
                        for (int mt = 0; mt < 4; mt++) {
                            MMA_BF16(acc[mt][2 * ntp],     ah[mt], bh + 0);
                            MMA_BF16(acc[mt][2 * ntp + 1], ah[mt], bh + 2);
                            MMA_BF16(acc[mt][2 * ntp],     ah[mt], bl + 0);
                            MMA_BF16(acc[mt][2 * ntp + 1], ah[mt], bl + 2);
                            MMA_BF16(acc[mt][2 * ntp],     al[mt], bh + 0);
                            MMA_BF16(acc[mt][2 * ntp + 1], al[mt], bh + 2);
                        }
                    }
                }
            }

            // ---- cvt + STS x(kblk+1) into stage (kblk+1)%3 ----
            if (more) {
                const int xs = (kblk + 1) % NSTG;
                const float* e = reinterpret_cast<const float*>(xr);
                uint32_t hw[8], lw[8];
#pragma unroll
                for (int q = 0; q < 8; q++) {
                    float v0 = e[2 * q], v1 = e[2 * q + 1];
                    float h0 = __bfloat162float(__float2bfloat16_rn(v0));
                    float h1 = __bfloat162float(__float2bfloat16_rn(v1));
                    hw[q] = pack2(h0, h1);
                    lw[q] = pack2(v0 - h0, v1 - h1);
                }
                unsigned char* xb = dyn + xs * XSTG;
#pragma unroll
                for (int j = 0; j < 2; j++) {
                    int swo = xm * 64 + (((xh2 * 2 + j) ^ xsw) << 4);
                    *reinterpret_cast<uint4*>(xb + swo) =
                        make_uint4(hw[4 * j], hw[4 * j + 1], hw[4 * j + 2], hw[4 * j + 3]);
                    *reinterpret_cast<uint4*>(xb + 8192 + swo) =
                        make_uint4(lw[4 * j], lw[4 * j + 1], lw[4 * j + 2], lw[4 * j + 3]);
                }
            }
        }
        CP_WAIT0();
        __syncthreads();

        // ---- epilogue for this n-chunk ----
#pragma unroll
        for (int mt = 0; mt < 4; mt++)
#pragma unroll
            for (int rh = 0; rh < 2; rh++) {
                int ml = wm * 64 + mt * 16 + (lane >> 2) + rh * 8;
                int gm = row0 + ml;
                int b = gm / LSEQ;
                const float* a2 = g_att2 + (size_t)b * ATTD + nb * 128 + wn * 32;
                const float* wfp = wf_s + nb * 128 + wn * 32;
                float s = 0.f;
#pragma unroll
                for (int nt = 0; nt < 4; nt++) {
#pragma unroll
                    for (int e2 = 0; e2 < 2; e2++) {
                        int nn = nt * 8 + (lane & 3) * 2 + e2;
                        float v = acc[mt][nt][rh * 2 + e2] + __ldg(a2 + nn);
                        s += fmaxf(v, 0.f) * wfp[nn];
                    }
                }
                s += __shfl_xor_sync(0xFFFFFFFF, s, 1);
                s += __shfl_xor_sync(0xFFFFFFFF, s, 2);
                if ((lane & 3) == 0) atomicAdd(&att_acc[ml], s);
            }
        __syncthreads();
    }

    if (tid < TILE_M) g_att[row0 + tid] = att_acc[tid];
}

// ---------------------------------------------------------------------------
__global__ __launch_bounds__(256) void softmax_kernel(float* __restrict__ out_alpha) {
    int b = blockIdx.x, t = threadIdx.x;
    __shared__ float sred[256];
    float v = (t < LSEQ) ? g_att[b * LSEQ + t] : -1e30f;
    sred[t] = v;
    __syncthreads();
    for (int s = 128; s > 0; s >>= 1) {
        if (t < s) sred[t] = fmaxf(sred[t], sred[t + s]);
        __syncthreads();
    }
    float m = sred[0];
    __syncthreads();
    float e = (t < LSEQ) ? expf(v - m) : 0.f;
    sred[t] = e;
    __syncthreads();
    for (int s = 128; s > 0; s >>= 1) {
        if (t < s) sred[t] += sred[t + s];
        __syncthreads();
    }
    float inv = 1.f / sred[0];
    if (t < LSEQ) out_alpha[b * LSEQ + t] = e * inv;
}

__global__ __launch_bounds__(256) void z_kernel(
    const float* __restrict__ x, const float* __restrict__ alpha,
    float* __restrict__ out_z) {
    int b = blockIdx.y;
    int c4 = blockIdx.x * 256 + threadIdx.x;
    __shared__ float sal[LSEQ];
    for (int i = threadIdx.x; i < LSEQ; i += 256) sal[i] = alpha[b * LSEQ + i];
    __syncthreads();
    const float4* xp = reinterpret_cast<const float4*>(x + (size_t)b * LSEQ * ENC) + c4;
    float ax = 0.f, ay = 0.f, az = 0.f, aw = 0.f;
#pragma unroll 4
    for (int l = 0; l < LSEQ; l++) {
        float4 v = xp[(size_t)l * (ENC / 4)];
        float a = sal[l];
        ax += a * v.x; ay += a * v.y; az += a * v.z; aw += a * v.w;
    }
    float g = g_gate[b];
    float4 o;
    o.x = g * ax; o.y = g * ay; o.z = g * az; o.w = g * aw;
    reinterpret_cast<float4*>(out_z)[(size_t)b * (ENC / 4) + c4] = o;
}

// ---------------------------------------------------------------------------
extern "C" void kernel_launch(void* const* d_in, const int* in_sizes, int n_in,
                              void* d_out, int out_size) {
    const float* x      = (const float*)d_in[0];
    const float* h      = (const float*)d_in[1];
    const float* W_enc  = (const float*)d_in[2];
    const float* b_enc  = (const float*)d_in[3];
    const float* W_dec  = (const float*)d_in[4];
    const float* b_dec  = (const float*)d_in[5];
    const float* W_full = (const float*)d_in[6];
    // d_in[7] = b_full: softmax-invariant, unused.
    const float* W_beta = (const float*)d_in[8];
    const float* b_beta = (const float*)d_in[9];

    float* out = (float*)d_out;
    float* out_z = out;
    float* out_alpha = out + (size_t)BATCH * ENC;

    cudaFuncSetAttribute(att_gemm_mma, cudaFuncAttributeMaxDynamicSharedMemorySize, DYN_BYTES);

    prep_w<<<dim3(ENC / 64, ATTD / 64), 256>>>(W_enc);
    att2_kernel<<<BATCH, 256>>>(h, W_dec, b_dec, b_enc, W_beta, b_beta);
    att_gemm_mma<<<NCTA, 256, DYN_BYTES>>>(x, W_full);
    softmax_kernel<<<BATCH, 256>>>(out_alpha);
    z_kernel<<<dim3(ENC / 1024, BATCH), 256>>>(x, out_alpha, out_z);
}

// round 8
// speedup vs baseline: 1.0944x; 1.0944x over previous
#include <cuda_runtime.h>
#include <cuda_fp16.h>
#include <cstdint>
#include <math.h>

#define ENC 2048
#define DEC 512
#define ATTD 512
#define BATCH 256
#define LSEQ 196
#define MROWS (BATCH * LSEQ)      // 50176
#define TILE_M 128
#define NCTA (MROWS / TILE_M)     // 392
#define KBLK 32
#define NKB (ENC / KBLK)          // 64
#define NB_CHUNKS 4               // 512 / 128
#define NSTG 4
#define XSTG 16384                // x: 128 rows x 32k x 2B x 2(hi/lo)
#define WSTG 16384                // W: 128 rows x 32k x 2B x 2(hi/lo)
#define WBASE (NSTG * XSTG)       // 65536
#define DYN_BYTES (WBASE + NSTG * WSTG + 128)  // 131200
#define LO_SCALE 2048.0f
#define LO_INV   (1.0f / 2048.0f)

// ---------------- scratch globals ----------------
__device__ float g_att2[BATCH * ATTD];
__device__ float g_gate[BATCH];
__device__ float g_att[MROWS];
// W transposed + fp16-split: [hl][n=512][k=2048] fp16; hl=1 plane pre-scaled x2048
__device__ __align__(16) unsigned char g_Wt[2u * 512u * 2048u * 2u];

// ---------------- helpers ----------------
__device__ __forceinline__ uint32_t smem_u32(const void* p) {
    uint32_t a;
    asm("{ .reg .u64 t; cvta.to.shared.u64 t, %1; cvt.u32.u64 %0, t; }" : "=r"(a) : "l"(p));
    return a;
}
__device__ __forceinline__ uint32_t packh2(__half a, __half b) {
    __half2 t = __halves2half2(a, b);
    return *reinterpret_cast<uint32_t*>(&t);
}
#define LDSM_X4(r, addr) \
    asm volatile("ldmatrix.sync.aligned.m8n8.x4.shared.b16 {%0,%1,%2,%3}, [%4];" \
        : "=r"((r)[0]), "=r"((r)[1]), "=r"((r)[2]), "=r"((r)[3]) : "r"(addr))
// fp16 inputs, fp32 accumulate
#define MMA_F32(c, a, b) \
    asm volatile("mma.sync.aligned.m16n8k16.row.col.f32.f16.f16.f32 " \
        "{%0,%1,%2,%3}, {%4,%5,%6,%7}, {%8,%9}, {%0,%1,%2,%3};" \
        : "+f"((c)[0]), "+f"((c)[1]), "+f"((c)[2]), "+f"((c)[3]) \
        : "r"((a)[0]), "r"((a)[1]), "r"((a)[2]), "r"((a)[3]), "r"((b)[0]), "r"((b)[1]))
// fp16 inputs, fp16 accumulate (2 x f16x2 regs)
#define MMA_F16(c, a, b) \
    asm volatile("mma.sync.aligned.m16n8k16.row.col.f16.f16.f16.f16 " \
        "{%0,%1}, {%2,%3,%4,%5}, {%6,%7}, {%0,%1};" \
        : "+r"((c)[0]), "+r"((c)[1]) \
        : "r"((a)[0]), "r"((a)[1]), "r"((a)[2]), "r"((a)[3]), "r"((b)[0]), "r"((b)[1]))
#define CP_ASYNC16(dst, src) \
    asm volatile("cp.async.ca.shared.global [%0], [%1], 16;" :: "r"(dst), "l"(src) : "memory")
#define CP_COMMIT() asm volatile("cp.async.commit_group;" ::: "memory")
#define CP_WAIT2()  asm volatile("cp.async.wait_group 2;" ::: "memory")
#define CP_WAIT0()  asm volatile("cp.async.wait_group 0;" ::: "memory")

// ---------------------------------------------------------------------------
// prep_w: W_enc [2048 k][512 n] fp32 -> g_Wt fp16 [hl][n][k], lo plane x2048
// ---------------------------------------------------------------------------
__global__ __launch_bounds__(256) void prep_w(const float* __restrict__ W_enc) {
    __shared__ float tile[64][65];
    const int k0 = blockIdx.x * 64, n0 = blockIdx.y * 64;
    const int tid = threadIdx.x;
    for (int i = tid; i < 64 * 64; i += 256) {
        int kk = i >> 6, nn = i & 63;
        tile[kk][nn] = W_enc[(size_t)(k0 + kk) * ATTD + n0 + nn];
    }
    __syncthreads();
    for (int i = tid; i < 1024; i += 256) {
        int hl = i >> 9, rem = i & 511;
        int nn = rem >> 3, ch = rem & 7;
        uint32_t w[4];
#pragma unroll
        for (int j = 0; j < 4; j++) {
            float v0 = tile[ch * 8 + 2 * j][nn], v1 = tile[ch * 8 + 2 * j + 1][nn];
            __half h0 = __float2half_rn(v0), h1 = __float2half_rn(v1);
            if (hl == 0) {
                w[j] = packh2(h0, h1);
            } else {
                w[j] = packh2(__float2half_rn((v0 - __half2float(h0)) * LO_SCALE),
                              __float2half_rn((v1 - __half2float(h1)) * LO_SCALE));
            }
        }
        *reinterpret_cast<uint4*>(g_Wt + (size_t)hl * 2097152 +
                                  (size_t)(n0 + nn) * 4096 + (size_t)(k0 + ch * 8) * 2) =
            make_uint4(w[0], w[1], w[2], w[3]);
    }
}

// ---------------------------------------------------------------------------
// att2 + gate
// ---------------------------------------------------------------------------
__global__ __launch_bounds__(256) void att2_kernel(
    const float* __restrict__ h, const float* __restrict__ W_dec,
    const float* __restrict__ b_dec, const float* __restrict__ b_enc,
    const float* __restrict__ W_beta, const float* __restrict__ b_beta) {
    int b = blockIdx.x, t = threadIdx.x;
    __shared__ float hs[DEC];
    __shared__ float red[256];
    hs[t] = h[b * DEC + t];
    hs[t + 256] = h[b * DEC + t + 256];
    __syncthreads();
    float acc0 = 0.f, acc1 = 0.f;
#pragma unroll 8
    for (int k = 0; k < DEC; k++) {
        float hv = hs[k];
        acc0 += hv * W_dec[k * ATTD + t];
        acc1 += hv * W_dec[k * ATTD + t + 256];
    }
    g_att2[b * ATTD + t] = acc0 + b_dec[t] + b_enc[t];
    g_att2[b * ATTD + t + 256] = acc1 + b_dec[t + 256] + b_enc[t + 256];
    float p = hs[t] * W_beta[t] + hs[t + 256] * W_beta[t + 256];
    red[t] = p;
    __syncthreads();
    for (int s = 128; s > 0; s >>= 1) {
        if (t < s) red[t] += red[t + s];
        __syncthreads();
    }
    if (t == 0) g_gate[b] = 1.f / (1.f + expf(-(red[0] + b_beta[0])));
}

// ---------------------------------------------------------------------------
// Main GEMM: fp16 hi/lo. Pass1 xh*Wh fp32-acc; passes 2+3 (xh*Wl' + xl'*Wh)
// fp16-acc (lo planes pre-scaled x2048). 8 warps = 4(m) x 2(n); warp m32 x n64.
// 4 n-chunks of 128. 4-stage pipeline, 1 barrier/kblk, in-loop x conversion.
// ---------------------------------------------------------------------------
__global__ __launch_bounds__(256, 1) void att_gemm_mma(
    const float* __restrict__ x, const float* __restrict__ W_full) {
    extern __shared__ unsigned char dynraw[];
    __shared__ float wf_s[ATTD];
    __shared__ float att_acc[TILE_M];

    const int tid = threadIdx.x;
    const int lane = tid & 31;
    const int wid = tid >> 5;
    const int wm = wid >> 1;   // 0..3
    const int wn = wid & 1;    // 0..1
    const int row0 = blockIdx.x * TILE_M;

    uint32_t rawb = smem_u32(dynraw);
    uint32_t dynb = (rawb + 127u) & ~127u;
    unsigned char* dyn = dynraw + (dynb - rawb);

    for (int i = tid; i < ATTD; i += 256) wf_s[i] = W_full[i];
    if (tid < TILE_M) att_acc[tid] = 0.f;
    __syncthreads();

    // x loader: thread -> (row xm, 16-elem half xh2)
    const int xm = tid >> 1, xh2 = tid & 1;
    const int xsw = (xm >> 1) & 3;
    const float4* xg = reinterpret_cast<const float4*>(x) +
                       ((size_t)(row0 + xm) * ENC) / 4 + xh2 * 4;

    // ldmatrix lane geometry (4m x 2n; warp tile m32 x n64)
    const int a_r = wm * 32 + (lane & 7) + (lane & 8);
    const int a_hi = lane >> 4;
    const int b_r = wn * 64 + (lane & 7) + ((lane >> 1) & 8);
    const int b_hi = (lane >> 3) & 1;

    for (int nb = 0; nb < NB_CHUNKS; nb++) {
        float accF[2][8][4];
        uint32_t accH[2][8][2];
#pragma unroll
        for (int mt = 0; mt < 2; mt++)
#pragma unroll
            for (int nt = 0; nt < 8; nt++) {
#pragma unroll
                for (int q = 0; q < 4; q++) accF[mt][nt][q] = 0.f;
                accH[mt][nt][0] = 0u; accH[mt][nt][1] = 0u;
            }

        // ---- prologue: x stage 0 (LDG+cvt+STS), W stages 0..2 via cp.async ----
        {
            float4 x0[4];
#pragma unroll
            for (int j = 0; j < 4; j++) x0[j] = xg[j];
            const float* e = reinterpret_cast<const float*>(x0);
            uint32_t hw[8], lw[8];
#pragma unroll
            for (int q = 0; q < 8; q++) {
                float v0 = e[2 * q], v1 = e[2 * q + 1];
                __half h0 = __float2half_rn(v0), h1 = __float2half_rn(v1);
                hw[q] = packh2(h0, h1);
                lw[q] = packh2(__float2half_rn((v0 - __half2float(h0)) * LO_SCALE),
                               __float2half_rn((v1 - __half2float(h1)) * LO_SCALE));
            }
#pragma unroll
            for (int j = 0; j < 2; j++) {
                int swo = xm * 64 + (((xh2 * 2 + j) ^ xsw) << 4);
                *reinterpret_cast<uint4*>(dyn + swo) =
                    make_uint4(hw[4 * j], hw[4 * j + 1], hw[4 * j + 2], hw[4 * j + 3]);
                *reinterpret_cast<uint4*>(dyn + 8192 + swo) =
                    make_uint4(lw[4 * j], lw[4 * j + 1], lw[4 * j + 2], lw[4 * j + 3]);
            }
        }
#pragma unroll
        for (int p = 0; p < 3; p++) {
#pragma unroll
            for (int hl = 0; hl < 2; hl++)
#pragma unroll
                for (int j = 0; j < 2; j++) {
                    int i = tid + 256 * j;
                    int row = i >> 2, c = i & 3;
                    uint32_t dst = dynb + WBASE + p * WSTG + hl * 8192 +
                                   row * 64 + ((c ^ ((row >> 1) & 3)) << 4);
                    const unsigned char* src = g_Wt + (size_t)hl * 2097152 +
                        (size_t)(nb * 128 + row) * 4096 + (size_t)(p * KBLK + c * 8) * 2;
                    CP_ASYNC16(dst, src);
                }
            CP_COMMIT();
        }

        for (int kblk = 0; kblk < NKB; kblk++) {
            const int st = kblk & 3;
            const bool more = (kblk + 1 < NKB);
            float4 xr[4];
            if (more) {
                const float4* p = xg + (kblk + 1) * (KBLK / 4);
#pragma unroll
                for (int j = 0; j < 4; j++) xr[j] = p[j];
            }
            CP_WAIT2();
            __syncthreads();   // W(kblk) + x(kblk) visible to all

            // issue W(kblk+3) (or empty group to keep wait bookkeeping)
            if (kblk + 3 < NKB) {
                const int ws = (kblk + 3) & 3;
#pragma unroll
                for (int hl = 0; hl < 2; hl++)
#pragma unroll
                    for (int j = 0; j < 2; j++) {
                        int i = tid + 256 * j;
                        int row = i >> 2, c = i & 3;
                        uint32_t dst = dynb + WBASE + ws * WSTG + hl * 8192 +
                                       row * 64 + ((c ^ ((row >> 1) & 3)) << 4);
                        const unsigned char* src = g_Wt + (size_t)hl * 2097152 +
                            (size_t)(nb * 128 + row) * 4096 +
                            (size_t)((kblk + 3) * KBLK + c * 8) * 2;
                        CP_ASYNC16(dst, src);
                    }
            }
            CP_COMMIT();

            // ---- MMA on stage st ----
            {
                const uint32_t xsb = dynb + st * XSTG;
                const uint32_t wsb = dynb + WBASE + st * WSTG;
#pragma unroll
                for (int ks = 0; ks < 2; ks++) {
                    uint32_t ah[2][4], al[2][4];
#pragma unroll
                    for (int mt = 0; mt < 2; mt++) {
                        int row = a_r + mt * 16;
                        uint32_t ad = xsb + row * 64 +
                                      (((ks * 2 + a_hi) ^ ((row >> 1) & 3)) << 4);
                        LDSM_X4(ah[mt], ad);
                        LDSM_X4(al[mt], ad + 8192);
                    }
#pragma unroll
                    for (int ntp = 0; ntp < 4; ntp++) {
                        int row = b_r + ntp * 16;
                        uint32_t bd = wsb + row * 64 +
                                      (((ks * 2 + b_hi) ^ ((row >> 1) & 3)) << 4);
                        uint32_t bh[4], bl[4];
                        LDSM_X4(bh, bd);
                        LDSM_X4(bl, bd + 8192);
#pragma unroll
                        for (int mt = 0; mt < 2; mt++) {
                            // pass 1: hi*hi, fp32 acc
                            MMA_F32(accF[mt][2 * ntp],     ah[mt], bh + 0);
                            MMA_F32(accF[mt][2 * ntp + 1], ah[mt], bh + 2);
                            // pass 2: hi*lo', fp16 acc
                            MMA_F16(accH[mt][2 * ntp],     ah[mt], bl + 0);
                            MMA_F16(accH[mt][2 * ntp + 1], ah[mt], bl + 2);
                            // pass 3: lo'*hi, fp16 acc
                            MMA_F16(accH[mt][2 * ntp],     al[mt], bh + 0);
                            MMA_F16(accH[mt][2 * ntp + 1], al[mt], bh + 2);
                        }
                    }
                }
            }

            // ---- cvt + STS x(kblk+1) into stage (kblk+1)%4 ----
            if (more) {
                const int xs = (kblk + 1) & 3;
                const float* e = reinterpret_cast<const float*>(xr);
                uint32_t hw[8], lw[8];
#pragma unroll
                for (int q = 0; q < 8; q++) {
                    float v0 = e[2 * q], v1 = e[2 * q + 1];
                    __half h0 = __float2half_rn(v0), h1 = __float2half_rn(v1);
                    hw[q] = packh2(h0, h1);
                    lw[q] = packh2(__float2half_rn((v0 - __half2float(h0)) * LO_SCALE),
                                   __float2half_rn((v1 - __half2float(h1)) * LO_SCALE));
                }
                unsigned char* xb = dyn + xs * XSTG;
#pragma unroll
                for (int j = 0; j < 2; j++) {
                    int swo = xm * 64 + (((xh2 * 2 + j) ^ xsw) << 4);
                    *reinterpret_cast<uint4*>(xb + swo) =
                        make_uint4(hw[4 * j], hw[4 * j + 1], hw[4 * j + 2], hw[4 * j + 3]);
                    *reinterpret_cast<uint4*>(xb + 8192 + swo) =
                        make_uint4(lw[4 * j], lw[4 * j + 1], lw[4 * j + 2], lw[4 * j + 3]);
                }
            }
        }
        CP_WAIT0();
        __syncthreads();

        // ---- epilogue: att1 = accF + accH*LO_INV; relu; dot W_full ----
#pragma unroll
        for (int mt = 0; mt < 2; mt++)
#pragma unroll
            for (int rh = 0; rh < 2; rh++) {
                int ml = wm * 32 + mt * 16 + (lane >> 2) + rh * 8;
                int gm = row0 + ml;
                int b = gm / LSEQ;
                const float* a2 = g_att2 + (size_t)b * ATTD + nb * 128 + wn * 64;
                const float* wfp = wf_s + nb * 128 + wn * 64;
                float s = 0.f;
#pragma unroll
                for (int nt = 0; nt < 8; nt++) {
                    __half2 ch2 = *reinterpret_cast<__half2*>(&accH[mt][nt][rh]);
                    float2 cf = __half22float2(ch2);
#pragma unroll
                    for (int e2 = 0; e2 < 2; e2++) {
                        int nn = nt * 8 + (lane & 3) * 2 + e2;
                        float corr = (e2 ? cf.y : cf.x) * LO_INV;
                        float v = accF[mt][nt][rh * 2 + e2] + corr + __ldg(a2 + nn);
                        s += fmaxf(v, 0.f) * wfp[nn];
                    }
                }
                s += __shfl_xor_sync(0xFFFFFFFF, s, 1);
                s += __shfl_xor_sync(0xFFFFFFFF, s, 2);
                if ((lane & 3) == 0) atomicAdd(&att_acc[ml], s);
            }
        __syncthreads();
    }

    if (tid < TILE_M) g_att[row0 + tid] = att_acc[tid];
}

// ---------------------------------------------------------------------------
__global__ __launch_bounds__(256) void softmax_kernel(float* __restrict__ out_alpha) {
    int b = blockIdx.x, t = threadIdx.x;
    __shared__ float sred[256];
    float v = (t < LSEQ) ? g_att[b * LSEQ + t] : -1e30f;
    sred[t] = v;
    __syncthreads();
    for (int s = 128; s > 0; s >>= 1) {
        if (t < s) sred[t] = fmaxf(sred[t], sred[t + s]);
        __syncthreads();
    }
    float m = sred[0];
    __syncthreads();
    float e = (t < LSEQ) ? expf(v - m) : 0.f;
    sred[t] = e;
    __syncthreads();
    for (int s = 128; s > 0; s >>= 1) {
        if (t < s) sred[t] += sred[t + s];
        __syncthreads();
    }
    float inv = 1.f / sred[0];
    if (t < LSEQ) out_alpha[b * LSEQ + t] = e * inv;
}

__global__ __launch_bounds__(256) void z_kernel(
    const float* __restrict__ x, const float* __restrict__ alpha,
    float* __restrict__ out_z) {
    int b = blockIdx.y;
    int c4 = blockIdx.x * 256 + threadIdx.x;
    __shared__ float sal[LSEQ];
    for (int i = threadIdx.x; i < LSEQ; i += 256) sal[i] = alpha[b * LSEQ + i];
    __syncthreads();
    const float4* xp = reinterpret_cast<const float4*>(x + (size_t)b * LSEQ * ENC) + c4;
    float ax = 0.f, ay = 0.f, az = 0.f, aw = 0.f;
#pragma unroll 4
    for (int l = 0; l < LSEQ; l++) {
        float4 v = xp[(size_t)l * (ENC / 4)];
        float a = sal[l];
        ax += a * v.x; ay += a * v.y; az += a * v.z; aw += a * v.w;
    }
    float g = g_gate[b];
    float4 o;
    o.x = g * ax; o.y = g * ay; o.z = g * az; o.w = g * aw;
    reinterpret_cast<float4*>(out_z)[(size_t)b * (ENC / 4) + c4] = o;
}

// ---------------------------------------------------------------------------
extern "C" void kernel_launch(void* const* d_in, const int* in_sizes, int n_in,
                              void* d_out, int out_size) {
    const float* x      = (const float*)d_in[0];
    const float* h      = (const float*)d_in[1];
    const float* W_enc  = (const float*)d_in[2];
    const float* b_enc  = (const float*)d_in[3];
    const float* W_dec  = (const float*)d_in[4];
    const float* b_dec  = (const float*)d_in[5];
    const float* W_full = (const float*)d_in[6];
    // d_in[7] = b_full: softmax-invariant, unused.
    const float* W_beta = (const float*)d_in[8];
    const float* b_beta = (const float*)d_in[9];

    float* out = (float*)d_out;
    float* out_z = out;
    float* out_alpha = out + (size_t)BATCH * ENC;

    cudaFuncSetAttribute(att_gemm_mma, cudaFuncAttributeMaxDynamicSharedMemorySize, DYN_BYTES);

    prep_w<<<dim3(ENC / 64, ATTD / 64), 256>>>(W_enc);
    att2_kernel<<<BATCH, 256>>>(h, W_dec, b_dec, b_enc, W_beta, b_beta);
    att_gemm_mma<<<NCTA, 256, DYN_BYTES>>>(x, W_full);
    softmax_kernel<<<BATCH, 256>>>(out_alpha);
    z_kernel<<<dim3(ENC / 1024, BATCH), 256>>>(x, out_alpha, out_z);
}

// round 9
// speedup vs baseline: 1.2012x; 1.0976x over previous
#include <cuda_runtime.h>
#include <cuda_bf16.h>
#include <cstdint>
#include <math.h>

#define ENC 2048
#define DEC 512
#define ATTD 512
#define BATCH 256
#define LSEQ 196
#define MROWS (BATCH * LSEQ)      // 50176
#define TILE_M 128
#define NCTA (MROWS / TILE_M)     // 392
#define KBLK 32
#define NKB (ENC / KBLK)          // 64
#define NB_CHUNKS 2               // 512 / 256
#define NSTG 4
#define XSTG 16384                // x: 128 rows x 32k x 2B x 2(hi/lo)
#define WSTG 32768                // W: 256 rows x 32k x 2B x 2(hi/lo)
#define WBASE (NSTG * XSTG)       // 65536
#define DYN_BYTES (WBASE + NSTG * WSTG + 128)  // 196736
#define NTHREADS 512

// ---------------- scratch globals ----------------
__device__ float g_att2[BATCH * ATTD];
__device__ float g_gate[BATCH];
__device__ float g_att[MROWS];
// W transposed + bf16-split: [hl][n=512][k=2048] bf16
__device__ __align__(16) unsigned char g_Wt[2u * 512u * 2048u * 2u];

// ---------------- helpers ----------------
__device__ __forceinline__ uint32_t smem_u32(const void* p) {
    uint32_t a;
    asm("{ .reg .u64 t; cvta.to.shared.u64 t, %1; cvt.u32.u64 %0, t; }" : "=r"(a) : "l"(p));
    return a;
}
__device__ __forceinline__ uint32_t pack2(float a, float b) {
    __nv_bfloat162 t = __floats2bfloat162_rn(a, b);
    return *reinterpret_cast<uint32_t*>(&t);
}
#define LDSM_X4(r, addr) \
    asm volatile("ldmatrix.sync.aligned.m8n8.x4.shared.b16 {%0,%1,%2,%3}, [%4];" \
        : "=r"((r)[0]), "=r"((r)[1]), "=r"((r)[2]), "=r"((r)[3]) : "r"(addr))
#define MMA_BF16(c, a, b) \
    asm volatile("mma.sync.aligned.m16n8k16.row.col.f32.bf16.bf16.f32 " \
        "{%0,%1,%2,%3}, {%4,%5,%6,%7}, {%8,%9}, {%0,%1,%2,%3};" \
        : "+f"((c)[0]), "+f"((c)[1]), "+f"((c)[2]), "+f"((c)[3]) \
        : "r"((a)[0]), "r"((a)[1]), "r"((a)[2]), "r"((a)[3]), "r"((b)[0]), "r"((b)[1]))
#define CP_ASYNC16(dst, src) \
    asm volatile("cp.async.ca.shared.global [%0], [%1], 16;" :: "r"(dst), "l"(src) : "memory")
#define CP_COMMIT() asm volatile("cp.async.commit_group;" ::: "memory")
#define CP_WAIT2()  asm volatile("cp.async.wait_group 2;" ::: "memory")
#define CP_WAIT0()  asm volatile("cp.async.wait_group 0;" ::: "memory")

// ---------------------------------------------------------------------------
// prep_w: W_enc [2048 k][512 n] fp32 -> g_Wt bf16 [hl][n][k]
// ---------------------------------------------------------------------------
__global__ __launch_bounds__(256) void prep_w(const float* __restrict__ W_enc) {
    __shared__ float tile[64][65];
    const int k0 = blockIdx.x * 64, n0 = blockIdx.y * 64;
    const int tid = threadIdx.x;
    for (int i = tid; i < 64 * 64; i += 256) {
        int kk = i >> 6, nn = i & 63;
        tile[kk][nn] = W_enc[(size_t)(k0 + kk) * ATTD + n0 + nn];
    }
    __syncthreads();
    for (int i = tid; i < 1024; i += 256) {
        int hl = i >> 9, rem = i & 511;
        int nn = rem >> 3, ch = rem & 7;
        uint32_t w[4];
#pragma unroll
        for (int j = 0; j < 4; j++) {
            float v0 = tile[ch * 8 + 2 * j][nn], v1 = tile[ch * 8 + 2 * j + 1][nn];
            float h0 = __bfloat162float(__float2bfloat16_rn(v0));
            float h1 = __bfloat162float(__float2bfloat16_rn(v1));
            w[j] = hl ? pack2(v0 - h0, v1 - h1) : pack2(h0, h1);
        }
        *reinterpret_cast<uint4*>(g_Wt + (size_t)hl * 2097152 +
                                  (size_t)(n0 + nn) * 4096 + (size_t)(k0 + ch * 8) * 2) =
            make_uint4(w[0], w[1], w[2], w[3]);
    }
}

// ---------------------------------------------------------------------------
// att2 + gate
// ---------------------------------------------------------------------------
__global__ __launch_bounds__(256) void att2_kernel(
    const float* __restrict__ h, const float* __restrict__ W_dec,
    const float* __restrict__ b_dec, const float* __restrict__ b_enc,
    const float* __restrict__ W_beta, const float* __restrict__ b_beta) {
    int b = blockIdx.x, t = threadIdx.x;
    __shared__ float hs[DEC];
    __shared__ float red[256];
    hs[t] = h[b * DEC + t];
    hs[t + 256] = h[b * DEC + t + 256];
    __syncthreads();
    float acc0 = 0.f, acc1 = 0.f;
#pragma unroll 8
    for (int k = 0; k < DEC; k++) {
        float hv = hs[k];
        acc0 += hv * W_dec[k * ATTD + t];
        acc1 += hv * W_dec[k * ATTD + t + 256];
    }
    g_att2[b * ATTD + t] = acc0 + b_dec[t] + b_enc[t];
    g_att2[b * ATTD + t + 256] = acc1 + b_dec[t + 256] + b_enc[t + 256];
    float p = hs[t] * W_beta[t] + hs[t + 256] * W_beta[t + 256];
    red[t] = p;
    __syncthreads();
    for (int s = 128; s > 0; s >>= 1) {
        if (t < s) red[t] += red[t + s];
        __syncthreads();
    }
    if (t == 0) g_gate[b] = 1.f / (1.f + expf(-(red[0] + b_beta[0])));
}

// ---------------------------------------------------------------------------
// Main GEMM: 3-pass bf16 mma.sync, 4-stage pipeline, 512 threads (16 warps).
// warps = 4(m) x 4(n); warp tile m32 x n64 -> 4 warps/SMSP for latency cover.
// 2 n-chunks of 256. acc=64 regs/thread, target <=128 total (no spill).
// ---------------------------------------------------------------------------
__global__ __launch_bounds__(NTHREADS, 1) void att_gemm_mma(
    const float* __restrict__ x, const float* __restrict__ W_full) {
    extern __shared__ unsigned char dynraw[];
    __shared__ float wf_s[ATTD];
    __shared__ float att_acc[TILE_M];

    const int tid = threadIdx.x;
    const int lane = tid & 31;
    const int wid = tid >> 5;
    const int wm = wid >> 2;   // 0..3
    const int wn = wid & 3;    // 0..3
    const int row0 = blockIdx.x * TILE_M;

    uint32_t rawb = smem_u32(dynraw);
    uint32_t dynb = (rawb + 127u) & ~127u;
    unsigned char* dyn = dynraw + (dynb - rawb);

    wf_s[tid] = W_full[tid];
    if (tid < TILE_M) att_acc[tid] = 0.f;
    __syncthreads();

    // x loader: thread -> (row xm = tid>>2, 8-elem quarter xq = tid&3)
    const int xm = tid >> 2, xq = tid & 3;
    const int xsw = (xm >> 1) & 3;
    const float4* xg = reinterpret_cast<const float4*>(x) +
                       ((size_t)(row0 + xm) * ENC) / 4 + xq * 2;

    // ldmatrix lane geometry (4m x 4n; warp tile m32 x n64)
    const int a_r = wm * 32 + (lane & 7) + (lane & 8);
    const int a_hi = lane >> 4;
    const int b_r = wn * 64 + (lane & 7) + ((lane >> 1) & 8);
    const int b_hi = (lane >> 3) & 1;

    for (int nb = 0; nb < NB_CHUNKS; nb++) {
        float acc[2][8][4];
#pragma unroll
        for (int mt = 0; mt < 2; mt++)
#pragma unroll
            for (int nt = 0; nt < 8; nt++)
#pragma unroll
                for (int q = 0; q < 4; q++) acc[mt][nt][q] = 0.f;

        // ---- prologue: x stage 0 (LDG+cvt+STS), W stages 0..2 via cp.async ----
        {
            float4 x0 = xg[0], x1 = xg[1];
            float e[8] = {x0.x, x0.y, x0.z, x0.w, x1.x, x1.y, x1.z, x1.w};
            uint32_t hw[4], lw[4];
#pragma unroll
            for (int q = 0; q < 4; q++) {
                float v0 = e[2 * q], v1 = e[2 * q + 1];
                float h0 = __bfloat162float(__float2bfloat16_rn(v0));
                float h1 = __bfloat162float(__float2bfloat16_rn(v1));
                hw[q] = pack2(h0, h1);
                lw[q] = pack2(v0 - h0, v1 - h1);
            }
            int swo = xm * 64 + ((xq ^ xsw) << 4);
            *reinterpret_cast<uint4*>(dyn + swo) = make_uint4(hw[0], hw[1], hw[2], hw[3]);
            *reinterpret_cast<uint4*>(dyn + 8192 + swo) = make_uint4(lw[0], lw[1], lw[2], lw[3]);
        }
#pragma unroll
        for (int p = 0; p < 3; p++) {
#pragma unroll
            for (int hl = 0; hl < 2; hl++)
#pragma unroll
                for (int j = 0; j < 2; j++) {
                    int i = tid + NTHREADS * j;
                    int row = i >> 2, c = i & 3;
                    uint32_t dst = dynb + WBASE + p * WSTG + hl * 16384 +
                                   row * 64 + ((c ^ ((row >> 1) & 3)) << 4);
                    const unsigned char* src = g_Wt + (size_t)hl * 2097152 +
                        (size_t)(nb * 256 + row) * 4096 + (size_t)(p * KBLK + c * 8) * 2;
                    CP_ASYNC16(dst, src);
                }
            CP_COMMIT();
        }

        for (int kblk = 0; kblk < NKB; kblk++) {
            const int st = kblk & 3;
            const bool more = (kblk + 1 < NKB);
            float4 xr0, xr1;
            if (more) {
                const float4* p = xg + (kblk + 1) * (KBLK / 4);
                xr0 = p[0]; xr1 = p[1];
            }
            CP_WAIT2();
            __syncthreads();   // stage kblk%4 (W + x) visible

            // issue W(kblk+3) into stage (kblk+3)%4 (or empty group)
            if (kblk + 3 < NKB) {
                const int ws = (kblk + 3) & 3;
#pragma unroll
                for (int hl = 0; hl < 2; hl++)
#pragma unroll
                    for (int j = 0; j < 2; j++) {
                        int i = tid + NTHREADS * j;
                        int row = i >> 2, c = i & 3;
                        uint32_t dst = dynb + WBASE + ws * WSTG + hl * 16384 +
                                       row * 64 + ((c ^ ((row >> 1) & 3)) << 4);
                        const unsigned char* src = g_Wt + (size_t)hl * 2097152 +
                            (size_t)(nb * 256 + row) * 4096 +
                            (size_t)((kblk + 3) * KBLK + c * 8) * 2;
                        CP_ASYNC16(dst, src);
                    }
            }
            CP_COMMIT();

            // ---- MMA on stage st ----
            {
                const uint32_t xsb = dynb + st * XSTG;
                const uint32_t wsb = dynb + WBASE + st * WSTG;
#pragma unroll
                for (int ks = 0; ks < 2; ks++) {
                    uint32_t ah[2][4], al[2][4];
#pragma unroll
                    for (int mt = 0; mt < 2; mt++) {
                        int row = a_r + mt * 16;
                        uint32_t ad = xsb + row * 64 +
                                      (((ks * 2 + a_hi) ^ ((row >> 1) & 3)) << 4);
                        LDSM_X4(ah[mt], ad);
                        LDSM_X4(al[mt], ad + 8192);
                    }
#pragma unroll
                    for (int ntp = 0; ntp < 4; ntp++) {
                        int row = b_r + ntp * 16;
                        uint32_t bd = wsb + row * 64 +
                                      (((ks * 2 + b_hi) ^ ((row >> 1) & 3)) << 4);
                        uint32_t bh[4], bl[4];
                        LDSM_X4(bh, bd);
                        LDSM_X4(bl, bd + 16384);
#pragma unroll
                        for (int mt = 0; mt < 2; mt++) {
                            MMA_BF16(acc[mt][2 * ntp],     ah[mt], bh + 0);
                            MMA_BF16(acc[mt][2 * ntp + 1], ah[mt], bh + 2);
                            MMA_BF16(acc[mt][2 * ntp],     ah[mt], bl + 0);
                            MMA_BF16(acc[mt][2 * ntp + 1], ah[mt], bl + 2);
                            MMA_BF16(acc[mt][2 * ntp],     al[mt], bh + 0);
                            MMA_BF16(acc[mt][2 * ntp + 1], al[mt], bh + 2);
                        }
                    }
                }
            }

            // ---- cvt + STS x(kblk+1) into stage (kblk+1)%4 ----
            if (more) {
                const int xs = (kblk + 1) & 3;
                float e[8] = {xr0.x, xr0.y, xr0.z, xr0.w, xr1.x, xr1.y, xr1.z, xr1.w};
                uint32_t hw[4], lw[4];
#pragma unroll
                for (int q = 0; q < 4; q++) {
                    float v0 = e[2 * q], v1 = e[2 * q + 1];
                    float h0 = __bfloat162float(__float2bfloat16_rn(v0));
                    float h1 = __bfloat162float(__float2bfloat16_rn(v1));
                    hw[q] = pack2(h0, h1);
                    lw[q] = pack2(v0 - h0, v1 - h1);
                }
                unsigned char* xb = dyn + xs * XSTG;
                int swo = xm * 64 + ((xq ^ xsw) << 4);
                *reinterpret_cast<uint4*>(xb + swo) = make_uint4(hw[0], hw[1], hw[2], hw[3]);
                *reinterpret_cast<uint4*>(xb + 8192 + swo) = make_uint4(lw[0], lw[1], lw[2], lw[3]);
            }
        }
        CP_WAIT0();
        __syncthreads();

        // ---- epilogue for this n-chunk ----
#pragma unroll
        for (int mt = 0; mt < 2; mt++)
#pragma unroll
            for (int rh = 0; rh < 2; rh++) {
                int ml = wm * 32 + mt * 16 + (lane >> 2) + rh * 8;
                int gm = row0 + ml;
                int b = gm / LSEQ;
                const float* a2 = g_att2 + (size_t)b * ATTD + nb * 256 + wn * 64;
                const float* wfp = wf_s + nb * 256 + wn * 64;
                float s = 0.f;
#pragma unroll
                for (int nt = 0; nt < 8; nt++) {
#pragma unroll
                    for (int e2 = 0; e2 < 2; e2++) {
                        int nn = nt * 8 + (lane & 3) * 2 + e2;
                        float v = acc[mt][nt][rh * 2 + e2] + __ldg(a2 + nn);
                        s += fmaxf(v, 0.f) * wfp[nn];
                    }
                }
                s += __shfl_xor_sync(0xFFFFFFFF, s, 1);
                s += __shfl_xor_sync(0xFFFFFFFF, s, 2);
                if ((lane & 3) == 0) atomicAdd(&att_acc[ml], s);
            }
        __syncthreads();
    }

    if (tid < TILE_M) g_att[row0 + tid] = att_acc[tid];
}

// ---------------------------------------------------------------------------
__global__ __launch_bounds__(256) void softmax_kernel(float* __restrict__ out_alpha) {
    int b = blockIdx.x, t = threadIdx.x;
    __shared__ float sred[256];
    float v = (t < LSEQ) ? g_att[b * LSEQ + t] : -1e30f;
    sred[t] = v;
    __syncthreads();
    for (int s = 128; s > 0; s >>= 1) {
        if (t < s) sred[t] = fmaxf(sred[t], sred[t + s]);
        __syncthreads();
    }
    float m = sred[0];
    __syncthreads();
    float e = (t < LSEQ) ? expf(v - m) : 0.f;
    sred[t] = e;
    __syncthreads();
    for (int s = 128; s > 0; s >>= 1) {
        if (t < s) sred[t] += sred[t + s];
        __syncthreads();
    }
    float inv = 1.f / sred[0];
    if (t < LSEQ) out_alpha[b * LSEQ + t] = e * inv;
}

__global__ __launch_bounds__(256) void z_kernel(
    const float* __restrict__ x, const float* __restrict__ alpha,
    float* __restrict__ out_z) {
    int b = blockIdx.y;
    int c4 = blockIdx.x * 256 + threadIdx.x;
    __shared__ float sal[LSEQ];
    for (int i = threadIdx.x; i < LSEQ; i += 256) sal[i] = alpha[b * LSEQ + i];
    __syncthreads();
    const float4* xp = reinterpret_cast<const float4*>(x + (size_t)b * LSEQ * ENC) + c4;
    float ax = 0.f, ay = 0.f, az = 0.f, aw = 0.f;
#pragma unroll 4
    for (int l = 0; l < LSEQ; l++) {
        float4 v = xp[(size_t)l * (ENC / 4)];
        float a = sal[l];
        ax += a * v.x; ay += a * v.y; az += a * v.z; aw += a * v.w;
    }
    float g = g_gate[b];
    float4 o;
    o.x = g * ax; o.y = g * ay; o.z = g * az; o.w = g * aw;
    reinterpret_cast<float4*>(out_z)[(size_t)b * (ENC / 4) + c4] = o;
}

// ---------------------------------------------------------------------------
extern "C" void kernel_launch(void* const* d_in, const int* in_sizes, int n_in,
                              void* d_out, int out_size) {
    const float* x      = (const float*)d_in[0];
    const float* h      = (const float*)d_in[1];
    const float* W_enc  = (const float*)d_in[2];
    const float* b_enc  = (const float*)d_in[3];
    const float* W_dec  = (const float*)d_in[4];
    const float* b_dec  = (const float*)d_in[5];
    const float* W_full = (const float*)d_in[6];
    // d_in[7] = b_full: softmax-invariant, unused.
    const float* W_beta = (const float*)d_in[8];
    const float* b_beta = (const float*)d_in[9];

    float* out = (float*)d_out;
    float* out_z = out;
    float* out_alpha = out + (size_t)BATCH * ENC;

    cudaFuncSetAttribute(att_gemm_mma, cudaFuncAttributeMaxDynamicSharedMemorySize, DYN_BYTES);

    prep_w<<<dim3(ENC / 64, ATTD / 64), 256>>>(W_enc);
    att2_kernel<<<BATCH, 256>>>(h, W_dec, b_dec, b_enc, W_beta, b_beta);
    att_gemm_mma<<<NCTA, NTHREADS, DYN_BYTES>>>(x, W_full);
    softmax_kernel<<<BATCH, 256>>>(out_alpha);
    z_kernel<<<dim3(ENC / 1024, BATCH), 256>>>(x, out_alpha, out_z);
}

// round 10
// speedup vs baseline: 2.1791x; 1.8140x over previous
#include <cuda_runtime.h>
#include <cuda_fp16.h>
#include <cstdint>
#include <math.h>

#define ENC 2048
#define DEC 512
#define ATTD 512
#define BATCH 256
#define LSEQ 196
#define MROWS (BATCH * LSEQ)      // 50176
#define TILE_M 128
#define NCTA (MROWS / TILE_M)     // 392
#define KBLK 32
#define NKB (ENC / KBLK)          // 64
#define NB_CHUNKS 2               // 512 / 256
#define NSTG 4
#define XSTG 8192                 // x: 128 rows x 32k x 2B
#define WSTG 16384                // W: 256 rows x 32k x 2B
#define WBASE (NSTG * XSTG)       // 32768
#define DYN_BYTES (WBASE + NSTG * WSTG + 128)  // 98432
#define NTHREADS 512

// ---------------- scratch globals ----------------
__device__ float g_att2[BATCH * ATTD];
__device__ float g_gate[BATCH];
__device__ float g_att[MROWS];
// W transposed fp16: [n=512][k=2048]
__device__ __align__(16) unsigned char g_Wt[512u * 2048u * 2u];

// ---------------- helpers ----------------
__device__ __forceinline__ uint32_t smem_u32(const void* p) {
    uint32_t a;
    asm("{ .reg .u64 t; cvta.to.shared.u64 t, %1; cvt.u32.u64 %0, t; }" : "=r"(a) : "l"(p));
    return a;
}
__device__ __forceinline__ uint32_t packh2(__half a, __half b) {
    __half2 t = __halves2half2(a, b);
    return *reinterpret_cast<uint32_t*>(&t);
}
#define LDSM_X4(r, addr) \
    asm volatile("ldmatrix.sync.aligned.m8n8.x4.shared.b16 {%0,%1,%2,%3}, [%4];" \
        : "=r"((r)[0]), "=r"((r)[1]), "=r"((r)[2]), "=r"((r)[3]) : "r"(addr))
#define MMA_F16F32(c, a, b) \
    asm volatile("mma.sync.aligned.m16n8k16.row.col.f32.f16.f16.f32 " \
        "{%0,%1,%2,%3}, {%4,%5,%6,%7}, {%8,%9}, {%0,%1,%2,%3};" \
        : "+f"((c)[0]), "+f"((c)[1]), "+f"((c)[2]), "+f"((c)[3]) \
        : "r"((a)[0]), "r"((a)[1]), "r"((a)[2]), "r"((a)[3]), "r"((b)[0]), "r"((b)[1]))
#define CP_ASYNC16(dst, src) \
    asm volatile("cp.async.ca.shared.global [%0], [%1], 16;" :: "r"(dst), "l"(src) : "memory")
#define CP_COMMIT() asm volatile("cp.async.commit_group;" ::: "memory")
#define CP_WAIT2()  asm volatile("cp.async.wait_group 2;" ::: "memory")
#define CP_WAIT0()  asm volatile("cp.async.wait_group 0;" ::: "memory")

// ---------------------------------------------------------------------------
// prep_w: W_enc [2048 k][512 n] fp32 -> g_Wt fp16 [n][k]
// ---------------------------------------------------------------------------
__global__ __launch_bounds__(256) void prep_w(const float* __restrict__ W_enc) {
    __shared__ float tile[64][65];
    const int k0 = blockIdx.x * 64, n0 = blockIdx.y * 64;
    const int tid = threadIdx.x;
    for (int i = tid; i < 64 * 64; i += 256) {
        int kk = i >> 6, nn = i & 63;
        tile[kk][nn] = W_enc[(size_t)(k0 + kk) * ATTD + n0 + nn];
    }
    __syncthreads();
    for (int i = tid; i < 512; i += 256) {
        int nn = i >> 3, ch = i & 7;
        uint32_t w[4];
#pragma unroll
        for (int j = 0; j < 4; j++) {
            w[j] = packh2(__float2half_rn(tile[ch * 8 + 2 * j][nn]),
                          __float2half_rn(tile[ch * 8 + 2 * j + 1][nn]));
        }
        *reinterpret_cast<uint4*>(g_Wt + (size_t)(n0 + nn) * 4096 +
                                  (size_t)(k0 + ch * 8) * 2) =
            make_uint4(w[0], w[1], w[2], w[3]);
    }
}

// ---------------------------------------------------------------------------
// att2 + gate (fp32, unchanged)
// ---------------------------------------------------------------------------
__global__ __launch_bounds__(256) void att2_kernel(
    const float* __restrict__ h, const float* __restrict__ W_dec,
    const float* __restrict__ b_dec, const float* __restrict__ b_enc,
    const float* __restrict__ W_beta, const float* __restrict__ b_beta) {
    int b = blockIdx.x, t = threadIdx.x;
    __shared__ float hs[DEC];
    __shared__ float red[256];
    hs[t] = h[b * DEC + t];
    hs[t + 256] = h[b * DEC + t + 256];
    __syncthreads();
    float acc0 = 0.f, acc1 = 0.f;
#pragma unroll 8
    for (int k = 0; k < DEC; k++) {
        float hv = hs[k];
        acc0 += hv * W_dec[k * ATTD + t];
        acc1 += hv * W_dec[k * ATTD + t + 256];
    }
    g_att2[b * ATTD + t] = acc0 + b_dec[t] + b_enc[t];
    g_att2[b * ATTD + t + 256] = acc1 + b_dec[t + 256] + b_enc[t + 256];
    float p = hs[t] * W_beta[t] + hs[t + 256] * W_beta[t + 256];
    red[t] = p;
    __syncthreads();
    for (int s = 128; s > 0; s >>= 1) {
        if (t < s) red[t] += red[t + s];
        __syncthreads();
    }
    if (t == 0) g_gate[b] = 1.f / (1.f + expf(-(red[0] + b_beta[0])));
}

// ---------------------------------------------------------------------------
// Main GEMM: single-pass fp16 mma.sync (fp32 acc), 4-stage pipeline,
// 512 threads = 16 warps (4m x 4n), warp tile m32 x n64, 2 n-chunks of 256.
// ---------------------------------------------------------------------------
__global__ __launch_bounds__(NTHREADS, 1) void att_gemm_mma(
    const float* __restrict__ x, const float* __restrict__ W_full) {
    extern __shared__ unsigned char dynraw[];
    __shared__ float wf_s[ATTD];
    __shared__ float att_acc[TILE_M];

    const int tid = threadIdx.x;
    const int lane = tid & 31;
    const int wid = tid >> 5;
    const int wm = wid >> 2;   // 0..3
    const int wn = wid & 3;    // 0..3
    const int row0 = blockIdx.x * TILE_M;

    uint32_t rawb = smem_u32(dynraw);
    uint32_t dynb = (rawb + 127u) & ~127u;
    unsigned char* dyn = dynraw + (dynb - rawb);

    wf_s[tid] = W_full[tid];
    if (tid < TILE_M) att_acc[tid] = 0.f;
    __syncthreads();

    // x loader: thread -> (row xm = tid>>2, 8-elem quarter xq = tid&3)
    const int xm = tid >> 2, xq = tid & 3;
    const int xsw = (xm >> 1) & 3;
    const float4* xg = reinterpret_cast<const float4*>(x) +
                       ((size_t)(row0 + xm) * ENC) / 4 + xq * 2;

    // ldmatrix lane geometry (4m x 4n; warp tile m32 x n64)
    const int a_r = wm * 32 + (lane & 7) + (lane & 8);
    const int a_hi = lane >> 4;
    const int b_r = wn * 64 + (lane & 7) + ((lane >> 1) & 8);
    const int b_hi = (lane >> 3) & 1;

    for (int nb = 0; nb < NB_CHUNKS; nb++) {
        float acc[2][8][4];
#pragma unroll
        for (int mt = 0; mt < 2; mt++)
#pragma unroll
            for (int nt = 0; nt < 8; nt++)
#pragma unroll
                for (int q = 0; q < 4; q++) acc[mt][nt][q] = 0.f;

        // ---- prologue: x stage 0 (LDG+cvt+STS), W stages 0..2 via cp.async ----
        {
            float4 x0 = xg[0], x1 = xg[1];
            float e[8] = {x0.x, x0.y, x0.z, x0.w, x1.x, x1.y, x1.z, x1.w};
            uint32_t hw[4];
#pragma unroll
            for (int q = 0; q < 4; q++)
                hw[q] = packh2(__float2half_rn(e[2 * q]), __float2half_rn(e[2 * q + 1]));
            int swo = xm * 64 + ((xq ^ xsw) << 4);
            *reinterpret_cast<uint4*>(dyn + swo) = make_uint4(hw[0], hw[1], hw[2], hw[3]);
        }
#pragma unroll
        for (int p = 0; p < 3; p++) {
#pragma unroll
            for (int j = 0; j < 2; j++) {
                int i = tid + NTHREADS * j;
                int row = i >> 2, c = i & 3;
                uint32_t dst = dynb + WBASE + p * WSTG +
                               row * 64 + ((c ^ ((row >> 1) & 3)) << 4);
                const unsigned char* src = g_Wt +
                    (size_t)(nb * 256 + row) * 4096 + (size_t)(p * KBLK + c * 8) * 2;
                CP_ASYNC16(dst, src);
            }
            CP_COMMIT();
        }

        for (int kblk = 0; kblk < NKB; kblk++) {
            const int st = kblk & 3;
            const bool more = (kblk + 1 < NKB);
            float4 xr0, xr1;
            if (more) {
                const float4* p = xg + (kblk + 1) * (KBLK / 4);
                xr0 = p[0]; xr1 = p[1];
            }
            CP_WAIT2();
            __syncthreads();   // stage kblk%4 (W + x) visible

            // issue W(kblk+3) (or empty group for bookkeeping)
            if (kblk + 3 < NKB) {
                const int ws = (kblk + 3) & 3;
#pragma unroll
                for (int j = 0; j < 2; j++) {
                    int i = tid + NTHREADS * j;
                    int row = i >> 2, c = i & 3;
                    uint32_t dst = dynb + WBASE + ws * WSTG +
                                   row * 64 + ((c ^ ((row >> 1) & 3)) << 4);
                    const unsigned char* src = g_Wt +
                        (size_t)(nb * 256 + row) * 4096 +
                        (size_t)((kblk + 3) * KBLK + c * 8) * 2;
                    CP_ASYNC16(dst, src);
                }
            }
            CP_COMMIT();

            // ---- MMA on stage st ----
            {
                const uint32_t xsb = dynb + st * XSTG;
                const uint32_t wsb = dynb + WBASE + st * WSTG;
#pragma unroll
                for (int ks = 0; ks < 2; ks++) {
                    uint32_t ah[2][4];
#pragma unroll
                    for (int mt = 0; mt < 2; mt++) {
                        int row = a_r + mt * 16;
                        uint32_t ad = xsb + row * 64 +
                                      (((ks * 2 + a_hi) ^ ((row >> 1) & 3)) << 4);
                        LDSM_X4(ah[mt], ad);
                    }
#pragma unroll
                    for (int ntp = 0; ntp < 4; ntp++) {
                        int row = b_r + ntp * 16;
                        uint32_t bd = wsb + row * 64 +
                                      (((ks * 2 + b_hi) ^ ((row >> 1) & 3)) << 4);
                        uint32_t bh[4];
                        LDSM_X4(bh, bd);
#pragma unroll
                        for (int mt = 0; mt < 2; mt++) {
                            MMA_F16F32(acc[mt][2 * ntp],     ah[mt], bh + 0);
                            MMA_F16F32(acc[mt][2 * ntp + 1], ah[mt], bh + 2);
                        }
                    }
                }
            }

            // ---- cvt + STS x(kblk+1) into stage (kblk+1)%4 ----
            if (more) {
                const int xs = (kblk + 1) & 3;
                float e[8] = {xr0.x, xr0.y, xr0.z, xr0.w, xr1.x, xr1.y, xr1.z, xr1.w};
                uint32_t hw[4];
#pragma unroll
                for (int q = 0; q < 4; q++)
                    hw[q] = packh2(__float2half_rn(e[2 * q]), __float2half_rn(e[2 * q + 1]));
                int swo = xm * 64 + ((xq ^ xsw) << 4);
                *reinterpret_cast<uint4*>(dyn + xs * XSTG + swo) =
                    make_uint4(hw[0], hw[1], hw[2], hw[3]);
            }
        }
        CP_WAIT0();
        __syncthreads();

        // ---- epilogue for this n-chunk ----
#pragma unroll
        for (int mt = 0; mt < 2; mt++)
#pragma unroll
            for (int rh = 0; rh < 2; rh++) {
                int ml = wm * 32 + mt * 16 + (lane >> 2) + rh * 8;
                int gm = row0 + ml;
                int b = gm / LSEQ;
                const float* a2 = g_att2 + (size_t)b * ATTD + nb * 256 + wn * 64;
                const float* wfp = wf_s + nb * 256 + wn * 64;
                float s = 0.f;
#pragma unroll
                for (int nt = 0; nt < 8; nt++) {
#pragma unroll
                    for (int e2 = 0; e2 < 2; e2++) {
                        int nn = nt * 8 + (lane & 3) * 2 + e2;
                        float v = acc[mt][nt][rh * 2 + e2] + __ldg(a2 + nn);
                        s += fmaxf(v, 0.f) * wfp[nn];
                    }
                }
                s += __shfl_xor_sync(0xFFFFFFFF, s, 1);
                s += __shfl_xor_sync(0xFFFFFFFF, s, 2);
                if ((lane & 3) == 0) atomicAdd(&att_acc[ml], s);
            }
        __syncthreads();
    }

    if (tid < TILE_M) g_att[row0 + tid] = att_acc[tid];
}

// ---------------------------------------------------------------------------
__global__ __launch_bounds__(256) void softmax_kernel(float* __restrict__ out_alpha) {
    int b = blockIdx.x, t = threadIdx.x;
    __shared__ float sred[256];
    float v = (t < LSEQ) ? g_att[b * LSEQ + t] : -1e30f;
    sred[t] = v;
    __syncthreads();
    for (int s = 128; s > 0; s >>= 1) {
        if (t < s) sred[t] = fmaxf(sred[t], sred[t + s]);
        __syncthreads();
    }
    float m = sred[0];
    __syncthreads();
    float e = (t < LSEQ) ? expf(v - m) : 0.f;
    sred[t] = e;
    __syncthreads();
    for (int s = 128; s > 0; s >>= 1) {
        if (t < s) sred[t] += sred[t + s];
        __syncthreads();
    }
    float inv = 1.f / sred[0];
    if (t < LSEQ) out_alpha[b * LSEQ + t] = e * inv;
}

__global__ __launch_bounds__(256) void z_kernel(
    const float* __restrict__ x, const float* __restrict__ alpha,
    float* __restrict__ out_z) {
    int b = blockIdx.y;
    int c4 = blockIdx.x * 256 + threadIdx.x;
    __shared__ float sal[LSEQ];
    for (int i = threadIdx.x; i < LSEQ; i += 256) sal[i] = alpha[b * LSEQ + i];
    __syncthreads();
    const float4* xp = reinterpret_cast<const float4*>(x + (size_t)b * LSEQ * ENC) + c4;
    float ax = 0.f, ay = 0.f, az = 0.f, aw = 0.f;
#pragma unroll 4
    for (int l = 0; l < LSEQ; l++) {
        float4 v = xp[(size_t)l * (ENC / 4)];
        float a = sal[l];
        ax += a * v.x; ay += a * v.y; az += a * v.z; aw += a * v.w;
    }
    float g = g_gate[b];
    float4 o;
    o.x = g * ax; o.y = g * ay; o.z = g * az; o.w = g * aw;
    reinterpret_cast<float4*>(out_z)[(size_t)b * (ENC / 4) + c4] = o;
}

// ---------------------------------------------------------------------------
extern "C" void kernel_launch(void* const* d_in, const int* in_sizes, int n_in,
                              void* d_out, int out_size) {
    const float* x      = (const float*)d_in[0];
    const float* h      = (const float*)d_in[1];
    const float* W_enc  = (const float*)d_in[2];
    const float* b_enc  = (const float*)d_in[3];
    const float* W_dec  = (const float*)d_in[4];
    const float* b_dec  = (const float*)d_in[5];
    const float* W_full = (const float*)d_in[6];
    // d_in[7] = b_full: softmax-invariant, unused.
    const float* W_beta = (const float*)d_in[8];
    const float* b_beta = (const float*)d_in[9];

    float* out = (float*)d_out;
    float* out_z = out;
    float* out_alpha = out + (size_t)BATCH * ENC;

    cudaFuncSetAttribute(att_gemm_mma, cudaFuncAttributeMaxDynamicSharedMemorySize, DYN_BYTES);

    prep_w<<<dim3(ENC / 64, ATTD / 64), 256>>>(W_enc);
    att2_kernel<<<BATCH, 256>>>(h, W_dec, b_dec, b_enc, W_beta, b_beta);
    att_gemm_mma<<<NCTA, NTHREADS, DYN_BYTES>>>(x, W_full);
    softmax_kernel<<<BATCH, 256>>>(out_alpha);
    z_kernel<<<dim3(ENC / 1024, BATCH), 256>>>(x, out_alpha, out_z);
}

// round 11
// speedup vs baseline: 2.3873x; 1.0955x over previous
#include <cuda_runtime.h>
#include <cuda_fp16.h>
#include <cstdint>
#include <math.h>

#define ENC 2048
#define DEC 512
#define ATTD 512
#define BATCH 256
#define LSEQ 196
#define MROWS (BATCH * LSEQ)      // 50176
#define TILE_M 128
#define NCTA (MROWS / TILE_M)     // 392
#define KBLK 64
#define NKB (ENC / KBLK)          // 32
#define NB_CHUNKS 2               // 512 / 256
#define NSTG 3
#define XSTG 16384                // x: 128 rows x 64k x 2B
#define WSTG 32768                // W: 256 rows x 64k x 2B
#define WBASE (NSTG * XSTG)       // 49152
#define DYN_BYTES (WBASE + NSTG * WSTG + 128)  // 147584
#define NTHREADS 512

// ---------------- scratch globals ----------------
__device__ float g_att2[BATCH * ATTD];
__device__ float g_gate[BATCH];
__device__ float g_att[MROWS];
// W transposed fp16: [n=512][k=2048]
__device__ __align__(16) unsigned char g_Wt[512u * 2048u * 2u];

// ---------------- helpers ----------------
__device__ __forceinline__ uint32_t smem_u32(const void* p) {
    uint32_t a;
    asm("{ .reg .u64 t; cvta.to.shared.u64 t, %1; cvt.u32.u64 %0, t; }" : "=r"(a) : "l"(p));
    return a;
}
__device__ __forceinline__ uint32_t packh2(__half a, __half b) {
    __half2 t = __halves2half2(a, b);
    return *reinterpret_cast<uint32_t*>(&t);
}
#define LDSM_X4(r, addr) \
    asm volatile("ldmatrix.sync.aligned.m8n8.x4.shared.b16 {%0,%1,%2,%3}, [%4];" \
        : "=r"((r)[0]), "=r"((r)[1]), "=r"((r)[2]), "=r"((r)[3]) : "r"(addr))
#define MMA_F16F32(c, a, b) \
    asm volatile("mma.sync.aligned.m16n8k16.row.col.f32.f16.f16.f32 " \
        "{%0,%1,%2,%3}, {%4,%5,%6,%7}, {%8,%9}, {%0,%1,%2,%3};" \
        : "+f"((c)[0]), "+f"((c)[1]), "+f"((c)[2]), "+f"((c)[3]) \
        : "r"((a)[0]), "r"((a)[1]), "r"((a)[2]), "r"((a)[3]), "r"((b)[0]), "r"((b)[1]))
#define CP_ASYNC16(dst, src) \
    asm volatile("cp.async.ca.shared.global [%0], [%1], 16;" :: "r"(dst), "l"(src) : "memory")
#define CP_COMMIT() asm volatile("cp.async.commit_group;" ::: "memory")
#define CP_WAIT1()  asm volatile("cp.async.wait_group 1;" ::: "memory")
#define CP_WAIT0()  asm volatile("cp.async.wait_group 0;" ::: "memory")

// ---------------------------------------------------------------------------
// prep_w: W_enc [2048 k][512 n] fp32 -> g_Wt fp16 [n][k]
// ---------------------------------------------------------------------------
__global__ __launch_bounds__(256) void prep_w(const float* __restrict__ W_enc) {
    __shared__ float tile[64][65];
    const int k0 = blockIdx.x * 64, n0 = blockIdx.y * 64;
    const int tid = threadIdx.x;
    for (int i = tid; i < 64 * 64; i += 256) {
        int kk = i >> 6, nn = i & 63;
        tile[kk][nn] = W_enc[(size_t)(k0 + kk) * ATTD + n0 + nn];
    }
    __syncthreads();
    for (int i = tid; i < 512; i += 256) {
        int nn = i >> 3, ch = i & 7;
        uint32_t w[4];
#pragma unroll
        for (int j = 0; j < 4; j++) {
            w[j] = packh2(__float2half_rn(tile[ch * 8 + 2 * j][nn]),
                          __float2half_rn(tile[ch * 8 + 2 * j + 1][nn]));
        }
        *reinterpret_cast<uint4*>(g_Wt + (size_t)(n0 + nn) * 4096 +
                                  (size_t)(k0 + ch * 8) * 2) =
            make_uint4(w[0], w[1], w[2], w[3]);
    }
}

// ---------------------------------------------------------------------------
// att2 + gate (fp32)
// ---------------------------------------------------------------------------
__global__ __launch_bounds__(256) void att2_kernel(
    const float* __restrict__ h, const float* __restrict__ W_dec,
    const float* __restrict__ b_dec, const float* __restrict__ b_enc,
    const float* __restrict__ W_beta, const float* __restrict__ b_beta) {
    int b = blockIdx.x, t = threadIdx.x;
    __shared__ float hs[DEC];
    __shared__ float red[256];
    hs[t] = h[b * DEC + t];
    hs[t + 256] = h[b * DEC + t + 256];
    __syncthreads();
    float acc0 = 0.f, acc1 = 0.f;
#pragma unroll 8
    for (int k = 0; k < DEC; k++) {
        float hv = hs[k];
        acc0 += hv * W_dec[k * ATTD + t];
        acc1 += hv * W_dec[k * ATTD + t + 256];
    }
    g_att2[b * ATTD + t] = acc0 + b_dec[t] + b_enc[t];
    g_att2[b * ATTD + t + 256] = acc1 + b_dec[t + 256] + b_enc[t + 256];
    float p = hs[t] * W_beta[t] + hs[t + 256] * W_beta[t + 256];
    red[t] = p;
    __syncthreads();
    for (int s = 128; s > 0; s >>= 1) {
        if (t < s) red[t] += red[t + s];
        __syncthreads();
    }
    if (t == 0) g_gate[b] = 1.f / (1.f + expf(-(red[0] + b_beta[0])));
}

// ---------------------------------------------------------------------------
// Main GEMM: single-pass fp16 mma.sync (fp32 acc), KBLK=64, 3-stage pipeline,
// 512 threads = 16 warps (4m x 4n), warp tile m32 x n64, 2 n-chunks of 256.
// 128-byte smem rows, swizzle chunk ^= (row & 7).
// ---------------------------------------------------------------------------
__global__ __launch_bounds__(NTHREADS, 1) void att_gemm_mma(
    const float* __restrict__ x, const float* __restrict__ W_full) {
    extern __shared__ unsigned char dynraw[];
    __shared__ float wf_s[ATTD];
    __shared__ float att_acc[TILE_M];

    const int tid = threadIdx.x;
    const int lane = tid & 31;
    const int wid = tid >> 5;
    const int wm = wid >> 2;   // 0..3
    const int wn = wid & 3;    // 0..3
    const int row0 = blockIdx.x * TILE_M;

    uint32_t rawb = smem_u32(dynraw);
    uint32_t dynb = (rawb + 127u) & ~127u;
    unsigned char* dyn = dynraw + (dynb - rawb);

    wf_s[tid] = W_full[tid];
    if (tid < TILE_M) att_acc[tid] = 0.f;
    __syncthreads();

    // x loader: 4 threads per row; xm row, xq = 16-elem (32B=2 chunk) quarter
    const int xm = tid >> 2, xq = tid & 3;
    const int xs7 = xm & 7;
    const float4* xg = reinterpret_cast<const float4*>(x) +
                       ((size_t)(row0 + xm) * ENC) / 4 + xq * 4;

    // ldmatrix lane geometry (4m x 4n; warp tile m32 x n64)
    const int a_r = wm * 32 + (lane & 15);
    const int a_hi = lane >> 4;
    const int b_r = wn * 64 + (lane & 7) + ((lane >> 1) & 8);
    const int b_hi = (lane >> 3) & 1;

    for (int nb = 0; nb < NB_CHUNKS; nb++) {
        float acc[2][8][4];
#pragma unroll
        for (int mt = 0; mt < 2; mt++)
#pragma unroll
            for (int nt = 0; nt < 8; nt++)
#pragma unroll
                for (int q = 0; q < 4; q++) acc[mt][nt][q] = 0.f;

        // ---- prologue: x stage 0 (LDG+cvt+STS), W stages 0,1 via cp.async ----
        {
            float4 v0 = xg[0], v1 = xg[1], v2 = xg[2], v3 = xg[3];
            float e[16] = {v0.x, v0.y, v0.z, v0.w, v1.x, v1.y, v1.z, v1.w,
                           v2.x, v2.y, v2.z, v2.w, v3.x, v3.y, v3.z, v3.w};
            uint32_t hw[8];
#pragma unroll
            for (int q = 0; q < 8; q++)
                hw[q] = packh2(__float2half_rn(e[2 * q]), __float2half_rn(e[2 * q + 1]));
            int c0 = 2 * xq;
            *reinterpret_cast<uint4*>(dyn + xm * 128 + ((c0 ^ xs7) << 4)) =
                make_uint4(hw[0], hw[1], hw[2], hw[3]);
            *reinterpret_cast<uint4*>(dyn + xm * 128 + (((c0 + 1) ^ xs7) << 4)) =
                make_uint4(hw[4], hw[5], hw[6], hw[7]);
        }
#pragma unroll
        for (int p = 0; p < 2; p++) {
#pragma unroll
            for (int j = 0; j < 4; j++) {
                int i = tid + NTHREADS * j;       // 0..2047
                int row = i >> 3, c = i & 7;
                uint32_t dst = dynb + WBASE + p * WSTG + row * 128 + ((c ^ (row & 7)) << 4);
                const unsigned char* src = g_Wt +
                    (size_t)(nb * 256 + row) * 4096 + (size_t)(p * KBLK + c * 8) * 2;
                CP_ASYNC16(dst, src);
            }
            CP_COMMIT();
        }

        for (int kblk = 0; kblk < NKB; kblk++) {
            const int st = kblk % NSTG;
            const bool more = (kblk + 1 < NKB);
            float4 xr0, xr1, xr2, xr3;
            if (more) {
                const float4* p = xg + (kblk + 1) * (KBLK / 4);
                xr0 = p[0]; xr1 = p[1]; xr2 = p[2]; xr3 = p[3];
            }
            CP_WAIT1();
            __syncthreads();   // stage kblk%3 (W + x) visible

            // issue W(kblk+2) into stage (kblk+2)%3 (or empty group)
            if (kblk + 2 < NKB) {
                const int ws = (kblk + 2) % NSTG;
#pragma unroll
                for (int j = 0; j < 4; j++) {
                    int i = tid + NTHREADS * j;
                    int row = i >> 3, c = i & 7;
                    uint32_t dst = dynb + WBASE + ws * WSTG + row * 128 +
                                   ((c ^ (row & 7)) << 4);
                    const unsigned char* src = g_Wt +
                        (size_t)(nb * 256 + row) * 4096 +
                        (size_t)((kblk + 2) * KBLK + c * 8) * 2;
                    CP_ASYNC16(dst, src);
                }
            }
            CP_COMMIT();

            // ---- MMA on stage st: 4 k16 steps ----
            {
                const uint32_t xsb = dynb + st * XSTG;
                const uint32_t wsb = dynb + WBASE + st * WSTG;
#pragma unroll
                for (int ks = 0; ks < 4; ks++) {
                    uint32_t ah[2][4];
#pragma unroll
                    for (int mt = 0; mt < 2; mt++) {
                        int row = a_r + mt * 16;
                        uint32_t ad = xsb + row * 128 +
                                      (((ks * 2 + a_hi) ^ (row & 7)) << 4);
                        LDSM_X4(ah[mt], ad);
                    }
#pragma unroll
                    for (int ntp = 0; ntp < 4; ntp++) {
                        int row = b_r + ntp * 16;
                        uint32_t bd = wsb + row * 128 +
                                      (((ks * 2 + b_hi) ^ (row & 7)) << 4);
                        uint32_t bh[4];
                        LDSM_X4(bh, bd);
#pragma unroll
                        for (int mt = 0; mt < 2; mt++) {
                            MMA_F16F32(acc[mt][2 * ntp],     ah[mt], bh + 0);
                            MMA_F16F32(acc[mt][2 * ntp + 1], ah[mt], bh + 2);
                        }
                    }
                }
            }

            // ---- cvt + STS x(kblk+1) into stage (kblk+1)%3 ----
            if (more) {
                const int xs = (kblk + 1) % NSTG;
                float e[16] = {xr0.x, xr0.y, xr0.z, xr0.w, xr1.x, xr1.y, xr1.z, xr1.w,
                               xr2.x, xr2.y, xr2.z, xr2.w, xr3.x, xr3.y, xr3.z, xr3.w};
                uint32_t hw[8];
#pragma unroll
                for (int q = 0; q < 8; q++)
                    hw[q] = packh2(__float2half_rn(e[2 * q]), __float2half_rn(e[2 * q + 1]));
                unsigned char* xb = dyn + xs * XSTG;
                int c0 = 2 * xq;
                *reinterpret_cast<uint4*>(xb + xm * 128 + ((c0 ^ xs7) << 4)) =
                    make_uint4(hw[0], hw[1], hw[2], hw[3]);
                *reinterpret_cast<uint4*>(xb + xm * 128 + (((c0 + 1) ^ xs7) << 4)) =
                    make_uint4(hw[4], hw[5], hw[6], hw[7]);
            }
        }
        CP_WAIT0();
        __syncthreads();

        // ---- epilogue for this n-chunk ----
#pragma unroll
        for (int mt = 0; mt < 2; mt++)
#pragma unroll
            for (int rh = 0; rh < 2; rh++) {
                int ml = wm * 32 + mt * 16 + (lane >> 2) + rh * 8;
                int gm = row0 + ml;
                int b = gm / LSEQ;
                const float* a2 = g_att2 + (size_t)b * ATTD + nb * 256 + wn * 64;
                const float* wfp = wf_s + nb * 256 + wn * 64;
                float s = 0.f;
#pragma unroll
                for (int nt = 0; nt < 8; nt++) {
#pragma unroll
                    for (int e2 = 0; e2 < 2; e2++) {
                        int nn = nt * 8 + (lane & 3) * 2 + e2;
                        float v = acc[mt][nt][rh * 2 + e2] + __ldg(a2 + nn);
                        s += fmaxf(v, 0.f) * wfp[nn];
                    }
                }
                s += __shfl_xor_sync(0xFFFFFFFF, s, 1);
                s += __shfl_xor_sync(0xFFFFFFFF, s, 2);
                if ((lane & 3) == 0) atomicAdd(&att_acc[ml], s);
            }
        __syncthreads();
    }

    if (tid < TILE_M) g_att[row0 + tid] = att_acc[tid];
}

// ---------------------------------------------------------------------------
__global__ __launch_bounds__(256) void softmax_kernel(float* __restrict__ out_alpha) {
    int b = blockIdx.x, t = threadIdx.x;
    __shared__ float sred[256];
    float v = (t < LSEQ) ? g_att[b * LSEQ + t] : -1e30f;
    sred[t] = v;
    __syncthreads();
    for (int s = 128; s > 0; s >>= 1) {
        if (t < s) sred[t] = fmaxf(sred[t], sred[t + s]);
        __syncthreads();
    }
    float m = sred[0];
    __syncthreads();
    float e = (t < LSEQ) ? expf(v - m) : 0.f;
    sred[t] = e;
    __syncthreads();
    for (int s = 128; s > 0; s >>= 1) {
        if (t < s) sred[t] += sred[t + s];
        __syncthreads();
    }
    float inv = 1.f / sred[0];
    if (t < LSEQ) out_alpha[b * LSEQ + t] = e * inv;
}

// ---------------------------------------------------------------------------
// z: one block per batch; each thread owns TWO float4 columns (2x MLP)
// ---------------------------------------------------------------------------
__global__ __launch_bounds__(256) void z_kernel(
    const float* __restrict__ x, const float* __restrict__ alpha,
    float* __restrict__ out_z) {
    int b = blockIdx.x;
    int t = threadIdx.x;
    __shared__ float sal[LSEQ];
    for (int i = t; i < LSEQ; i += 256) sal[i] = alpha[b * LSEQ + i];
    __syncthreads();
    const float4* xp = reinterpret_cast<const float4*>(x + (size_t)b * LSEQ * ENC);
    float4 a0 = {0.f, 0.f, 0.f, 0.f}, a1 = {0.f, 0.f, 0.f, 0.f};
#pragma unroll 2
    for (int l = 0; l < LSEQ; l++) {
        float a = sal[l];
        float4 v0 = __ldg(xp + (size_t)l * (ENC / 4) + t);
        float4 v1 = __ldg(xp + (size_t)l * (ENC / 4) + t + 256);
        a0.x += a * v0.x; a0.y += a * v0.y; a0.z += a * v0.z; a0.w += a * v0.w;
        a1.x += a * v1.x; a1.y += a * v1.y; a1.z += a * v1.z; a1.w += a * v1.w;
    }
    float g = g_gate[b];
    float4 o0 = {g * a0.x, g * a0.y, g * a0.z, g * a0.w};
    float4 o1 = {g * a1.x, g * a1.y, g * a1.z, g * a1.w};
    reinterpret_cast<float4*>(out_z)[(size_t)b * (ENC / 4) + t] = o0;
    reinterpret_cast<float4*>(out_z)[(size_t)b * (ENC / 4) + t + 256] = o1;
}

// ---------------------------------------------------------------------------
extern "C" void kernel_launch(void* const* d_in, const int* in_sizes, int n_in,
                              void* d_out, int out_size) {
    const float* x      = (const float*)d_in[0];
    const float* h      = (const float*)d_in[1];
    const float* W_enc  = (const float*)d_in[2];
    const float* b_enc  = (const float*)d_in[3];
    const float* W_dec  = (const float*)d_in[4];
    const float* b_dec  = (const float*)d_in[5];
    const float* W_full = (const float*)d_in[6];
    // d_in[7] = b_full: softmax-invariant, unused.
    const float* W_beta = (const float*)d_in[8];
    const float* b_beta = (const float*)d_in[9];

    float* out = (float*)d_out;
    float* out_z = out;
    float* out_alpha = out + (size_t)BATCH * ENC;

    cudaFuncSetAttribute(att_gemm_mma, cudaFuncAttributeMaxDynamicSharedMemorySize, DYN_BYTES);

    prep_w<<<dim3(ENC / 64, ATTD / 64), 256>>>(W_enc);
    att2_kernel<<<BATCH, 256>>>(h, W_dec, b_dec, b_enc, W_beta, b_beta);
    att_gemm_mma<<<NCTA, NTHREADS, DYN_BYTES>>>(x, W_full);
    softmax_kernel<<<BATCH, 256>>>(out_alpha);
    z_kernel<<<BATCH, 256>>>(x, out_alpha, out_z);
}